// round 11
// baseline (speedup 1.0000x reference)
#include <cuda_runtime.h>
#include <cstdint>

// Problem constants
#define NPTS   1048576
#define NC     32
#define NXc    64
#define Vv     (64*64*64)        // 262144
#define Bb     8
#define BV     (Bb*Vv)           // 2097152
#define HALFc  1.6f
#define RUNITc 20.0f             // fl(1/0.05f) == 20.0f — matches XLA's div->mul rewrite

// Output layout (float32, concatenated in reference tuple order)
#define OUT_PC      0
#define OUT_FEATS   (NPTS*3)                    // 3145728
#define OUT_COUNTS  (OUT_FEATS + BV*NC)         // 70254592
#define OUT_FLAG    (OUT_COUNTS + BV)           // 72351744

// Scratch: zero-initialized at module load; every kernel_launch execution
// restores it to zero (finalize zeroes only touched voxels), so the invariant
// holds across graph replays. No allocation anywhere.
__device__ float g_sums[(size_t)BV * NC];   // 256 MiB
__device__ float g_counts[BV];              // 8 MiB
__device__ float g_flag[Bb];

__device__ __forceinline__ void red_add_v4(float* addr, float4 v) {
    asm volatile("red.global.add.v4.f32 [%0], {%1, %2, %3, %4};"
                 :: "l"(addr), "f"(v.x), "f"(v.y), "f"(v.z), "f"(v.w)
                 : "memory");
}

__global__ __launch_bounds__(256)
void p2v_accum(const float* __restrict__ pc,
               const float* __restrict__ feat,
               const int*   __restrict__ bid,
               float* __restrict__ out_pc) {
    int i = blockIdx.x * blockDim.x + threadIdx.x;
    if (i >= NPTS) return;

    float x = pc[3*i + 0];
    float y = pc[3*i + 1];
    float z = pc[3*i + 2];

    bool valid = (fabsf(x) <= HALFc) & (fabsf(y) <= HALFc) & (fabsf(z) <= HALFc);

    // masked point cloud
    out_pc[3*i + 0] = valid ? x : 0.0f;
    out_pc[3*i + 1] = valid ? y : 0.0f;
    out_pc[3*i + 2] = valid ? z : 0.0f;

    int b = valid ? bid[i] : -1;

    // Per-warp dedup of the instance-flag store: one store per distinct
    // batch id present in the warp instead of one per point.
    unsigned active = __activemask();
    unsigned peers  = __match_any_sync(active, b);
    if (valid && (__ffs(peers) - 1) == (int)(threadIdx.x & 31)) {
        g_flag[b] = 1.0f;
    }

    if (!valid) return;

    // Match XLA exactly: (p + HALF) * fl(1/UNIT), both round-to-nearest.
    int ix = (int)__fmul_rn(__fadd_rn(x, HALFc), RUNITc);
    int iy = (int)__fmul_rn(__fadd_rn(y, HALFc), RUNITc);
    int iz = (int)__fmul_rn(__fadd_rn(z, HALFc), RUNITc);
    ix = min(max(ix, 0), NXc - 1);
    iy = min(max(iy, 0), NXc - 1);
    iz = min(max(iz, 0), NXc - 1);

    int lin = b * Vv + ix * (64*64) + iy * 64 + iz;

    atomicAdd(&g_counts[lin], 1.0f);

    // Feature rows are single-use: stream them (ldcs) so the 128 MB read
    // doesn't evict the atomic working set (sums lines + counts) from L2.
    const float4* f4 = reinterpret_cast<const float4*>(feat + (size_t)i * NC);
    float* dst = &g_sums[(size_t)lin * NC];
#pragma unroll
    for (int j = 0; j < NC / 4; j++) {
        float4 v = __ldcs(&f4[j]);
        red_add_v4(dst + 4*j, v);
    }
}

// K2: streaming finalize, 4 slots per thread spaced SLOTS/4 apart.
// The 4 count loads are independent (front-batched, L2-resident), then up to
// 4 independent predicated DRAM loads issue together — the count->sums chain
// latency is amortized over 4x the work. Streaming data uses ldcs/stcs so it
// cannot evict the counts array from L2.
#define SLOTS (BV * (NC / 4))           // 16777216
#define QSTEP (SLOTS / 4)               // 4194304

__global__ __launch_bounds__(256)
void p2v_finalize(float* __restrict__ out_feats,
                  float* __restrict__ out_counts,
                  float* __restrict__ out_flag) {
    int t = blockIdx.x * blockDim.x + threadIdx.x;

    int   q[4];
    float c[4];
#pragma unroll
    for (int k = 0; k < 4; k++) {
        q[k] = t + k * QSTEP;
        c[k] = g_counts[q[k] >> 3];        // 4 independent L2-resident loads
    }

    const float4 zero = make_float4(0.f, 0.f, 0.f, 0.f);
    bool   tch[4];
    float4 s[4];
#pragma unroll
    for (int k = 0; k < 4; k++) {
        tch[k] = (c[k] > 0.0f);
        s[k] = zero;
        if (tch[k])
            s[k] = __ldcs(reinterpret_cast<const float4*>(g_sums) + q[k]);
    }

#pragma unroll
    for (int k = 0; k < 4; k++) {
        float r = tch[k] ? __frcp_rn(c[k]) : 0.0f;   // avoid 0 * inf = NaN
        float4 o;
        o.x = s[k].x * r; o.y = s[k].y * r; o.z = s[k].z * r; o.w = s[k].w * r;
        __stcs(reinterpret_cast<float4*>(out_feats) + q[k], o);

        if (tch[k]) {
            // restore scratch invariant (untouched slots are already zero)
            __stcs(reinterpret_cast<float4*>(g_sums) + q[k], zero);
        }
        if ((q[k] & 7) == 0) {
            int vox = q[k] >> 3;
            __stcs(&out_counts[vox], c[k]);
            if (tch[k]) g_counts[vox] = 0.0f;
        }
    }

    if (blockIdx.x == 0 && threadIdx.x < Bb) {
        out_flag[threadIdx.x] = g_flag[threadIdx.x];
        g_flag[threadIdx.x] = 0.0f;
    }
}

extern "C" void kernel_launch(void* const* d_in, const int* in_sizes, int n_in,
                              void* d_out, int out_size) {
    const float* pc   = (const float*)d_in[0];
    const float* feat = (const float*)d_in[1];
    const int*   bid  = (const int*)  d_in[2];
    float* out = (float*)d_out;

    p2v_accum<<<(NPTS + 255) / 256, 256>>>(pc, feat, bid, out + OUT_PC);

    p2v_finalize<<<QSTEP / 256, 256>>>(out + OUT_FEATS,
                                       out + OUT_COUNTS,
                                       out + OUT_FLAG);
}

// round 14
// speedup vs baseline: 1.0032x; 1.0032x over previous
#include <cuda_runtime.h>
#include <cstdint>

// Problem constants
#define NPTS   1048576
#define NC     32
#define NXc    64
#define Vv     (64*64*64)        // 262144
#define Bb     8
#define BV     (Bb*Vv)           // 2097152
#define HALFc  1.6f
#define RUNITc 20.0f             // fl(1/0.05f) == 20.0f — matches XLA's div->mul rewrite

// Output layout (float32, concatenated in reference tuple order)
#define OUT_PC      0
#define OUT_FEATS   (NPTS*3)                    // 3145728
#define OUT_COUNTS  (OUT_FEATS + BV*NC)         // 70254592
#define OUT_FLAG    (OUT_COUNTS + BV)           // 72351744

// Scratch: zero-initialized at module load; every kernel_launch execution
// restores it to zero (finalize zeroes only touched voxels), so the invariant
// holds across graph replays. No allocation anywhere.
__device__ float g_sums[(size_t)BV * NC];   // 256 MiB
__device__ float g_counts[BV];              // 8 MiB
__device__ float g_flag[Bb];

__device__ __forceinline__ void red_add_v4(float* addr, float4 v) {
    asm volatile("red.global.add.v4.f32 [%0], {%1, %2, %3, %4};"
                 :: "l"(addr), "f"(v.x), "f"(v.y), "f"(v.z), "f"(v.w)
                 : "memory");
}

__global__ __launch_bounds__(256)
void p2v_accum(const float* __restrict__ pc,
               const float* __restrict__ feat,
               const int*   __restrict__ bid,
               float* __restrict__ out_pc) {
    int i = blockIdx.x * blockDim.x + threadIdx.x;
    if (i >= NPTS) return;

    float x = pc[3*i + 0];
    float y = pc[3*i + 1];
    float z = pc[3*i + 2];

    bool valid = (fabsf(x) <= HALFc) & (fabsf(y) <= HALFc) & (fabsf(z) <= HALFc);

    // masked point cloud
    out_pc[3*i + 0] = valid ? x : 0.0f;
    out_pc[3*i + 1] = valid ? y : 0.0f;
    out_pc[3*i + 2] = valid ? z : 0.0f;

    int b = valid ? bid[i] : -1;

    // Per-warp dedup of the instance-flag store: one store per distinct
    // batch id present in the warp instead of one per point.
    unsigned active = __activemask();
    unsigned peers  = __match_any_sync(active, b);
    if (valid && (__ffs(peers) - 1) == (int)(threadIdx.x & 31)) {
        g_flag[b] = 1.0f;
    }

    if (!valid) return;

    // Match XLA exactly: (p + HALF) * fl(1/UNIT), both round-to-nearest.
    int ix = (int)__fmul_rn(__fadd_rn(x, HALFc), RUNITc);
    int iy = (int)__fmul_rn(__fadd_rn(y, HALFc), RUNITc);
    int iz = (int)__fmul_rn(__fadd_rn(z, HALFc), RUNITc);
    ix = min(max(ix, 0), NXc - 1);
    iy = min(max(iy, 0), NXc - 1);
    iz = min(max(iz, 0), NXc - 1);

    int lin = b * Vv + ix * (64*64) + iy * 64 + iz;

    atomicAdd(&g_counts[lin], 1.0f);

    // Feature rows are single-use: stream them (ldcs) so the 128 MB read
    // doesn't evict the atomic working set (sums lines + counts) from L2.
    const float4* f4 = reinterpret_cast<const float4*>(feat + (size_t)i * NC);
    float* dst = &g_sums[(size_t)lin * NC];
#pragma unroll
    for (int j = 0; j < NC / 4; j++) {
        float4 v = __ldcs(&f4[j]);
        red_add_v4(dst + 4*j, v);
    }
}

// K2: streaming finalize, 4 slots per thread spaced SLOTS/4 apart.
// The 4 count loads are independent (front-batched, L2-resident), then up to
// 4 independent predicated DRAM loads issue together — the count->sums chain
// latency is amortized over 4x the work. Streaming data uses ldcs/stcs so it
// cannot evict the counts array from L2.
#define SLOTS (BV * (NC / 4))           // 16777216
#define QSTEP (SLOTS / 4)               // 4194304

__global__ __launch_bounds__(256)
void p2v_finalize(float* __restrict__ out_feats,
                  float* __restrict__ out_counts,
                  float* __restrict__ out_flag) {
    int t = blockIdx.x * blockDim.x + threadIdx.x;

    int   q[4];
    float c[4];
#pragma unroll
    for (int k = 0; k < 4; k++) {
        q[k] = t + k * QSTEP;
        c[k] = g_counts[q[k] >> 3];        // 4 independent L2-resident loads
    }

    const float4 zero = make_float4(0.f, 0.f, 0.f, 0.f);
    bool   tch[4];
    float4 s[4];
#pragma unroll
    for (int k = 0; k < 4; k++) {
        tch[k] = (c[k] > 0.0f);
        s[k] = zero;
        if (tch[k])
            s[k] = __ldcs(reinterpret_cast<const float4*>(g_sums) + q[k]);
    }

#pragma unroll
    for (int k = 0; k < 4; k++) {
        float r = tch[k] ? __frcp_rn(c[k]) : 0.0f;   // avoid 0 * inf = NaN
        float4 o;
        o.x = s[k].x * r; o.y = s[k].y * r; o.z = s[k].z * r; o.w = s[k].w * r;
        __stcs(reinterpret_cast<float4*>(out_feats) + q[k], o);

        if (tch[k]) {
            // restore scratch invariant (untouched slots are already zero)
            __stcs(reinterpret_cast<float4*>(g_sums) + q[k], zero);
        }
        if ((q[k] & 7) == 0) {
            int vox = q[k] >> 3;
            __stcs(&out_counts[vox], c[k]);
            if (tch[k]) g_counts[vox] = 0.0f;
        }
    }

    if (blockIdx.x == 0 && threadIdx.x < Bb) {
        out_flag[threadIdx.x] = g_flag[threadIdx.x];
        g_flag[threadIdx.x] = 0.0f;
    }
}

extern "C" void kernel_launch(void* const* d_in, const int* in_sizes, int n_in,
                              void* d_out, int out_size) {
    const float* pc   = (const float*)d_in[0];
    const float* feat = (const float*)d_in[1];
    const int*   bid  = (const int*)  d_in[2];
    float* out = (float*)d_out;

    p2v_accum<<<(NPTS + 255) / 256, 256>>>(pc, feat, bid, out + OUT_PC);

    p2v_finalize<<<QSTEP / 256, 256>>>(out + OUT_FEATS,
                                       out + OUT_COUNTS,
                                       out + OUT_FLAG);
}